// round 1
// baseline (speedup 1.0000x reference)
#include <cuda_runtime.h>
#include <math.h>

#define B_ 2
#define S_ 2048
#define D_ 2048
#define H_ 32
#define G_ 8
#define HD_ 64
#define GS_ (H_/G_)

// Scratch (device globals: no allocations allowed)
__device__ float g_q[(size_t)B_*S_*H_*HD_];
__device__ float g_k[(size_t)B_*S_*G_*HD_];
__device__ float g_v[(size_t)B_*S_*G_*HD_];
__device__ float g_ctx[(size_t)B_*S_*H_*HD_];

// ---------------------------------------------------------------------------
// NT GEMM: C[M,N] = A[M,K] @ B[N,K]^T   (both A and B row-major, K contiguous)
// Tile 128x64x16, 256 threads, 8x4 register tile per thread.
// Requires M%128==0, N%64==0, K%16==0 (true for all our shapes).
// ---------------------------------------------------------------------------
#define GBM 128
#define GBN 64
#define GBK 16

__global__ __launch_bounds__(256) void gemm_nt(
    const float* __restrict__ A, const float* __restrict__ Bm,
    float* __restrict__ C, int M, int N, int K)
{
    __shared__ __align__(16) float As[GBK][GBM];
    __shared__ __align__(16) float Bs[GBK][GBN];

    const int tid = threadIdx.x;
    const int m0  = blockIdx.y * GBM;
    const int n0  = blockIdx.x * GBN;
    const int rg  = tid >> 4;   // 0..15 -> rows rg*8 .. rg*8+7
    const int cg  = tid & 15;   // 0..15 -> cols cg*4 .. cg*4+3

    float acc[8][4];
    #pragma unroll
    for (int i = 0; i < 8; i++)
        #pragma unroll
        for (int j = 0; j < 4; j++) acc[i][j] = 0.f;

    for (int kb = 0; kb < K; kb += GBK) {
        // Load A tile: 128x16 floats = 512 float4, 2 per thread, stored transposed
        #pragma unroll
        for (int f = tid; f < 512; f += 256) {
            int row = f >> 2, kk = (f & 3) << 2;
            float4 v = *(const float4*)(A + (size_t)(m0 + row) * K + kb + kk);
            As[kk+0][row] = v.x; As[kk+1][row] = v.y;
            As[kk+2][row] = v.z; As[kk+3][row] = v.w;
        }
        // Load B tile: 64x16 floats = 256 float4, 1 per thread
        {
            int row = tid >> 2, kk = (tid & 3) << 2;
            float4 v = *(const float4*)(Bm + (size_t)(n0 + row) * K + kb + kk);
            Bs[kk+0][row] = v.x; Bs[kk+1][row] = v.y;
            Bs[kk+2][row] = v.z; Bs[kk+3][row] = v.w;
        }
        __syncthreads();

        #pragma unroll
        for (int k = 0; k < GBK; k++) {
            float4 a0 = *(const float4*)&As[k][rg * 8];
            float4 a1 = *(const float4*)&As[k][rg * 8 + 4];
            float4 b0 = *(const float4*)&Bs[k][cg * 4];
            float a[8] = {a0.x, a0.y, a0.z, a0.w, a1.x, a1.y, a1.z, a1.w};
            float b[4] = {b0.x, b0.y, b0.z, b0.w};
            #pragma unroll
            for (int i = 0; i < 8; i++)
                #pragma unroll
                for (int j = 0; j < 4; j++)
                    acc[i][j] = fmaf(a[i], b[j], acc[i][j]);
        }
        __syncthreads();
    }

    #pragma unroll
    for (int i = 0; i < 8; i++) {
        float4 o = make_float4(acc[i][0], acc[i][1], acc[i][2], acc[i][3]);
        *(float4*)(C + (size_t)(m0 + rg * 8 + i) * N + n0 + cg * 4) = o;
    }
}

// ---------------------------------------------------------------------------
// Fused RMSNorm + RoPE + scalar multiply. One warp per (b,s,head) row of 64.
// t layout: [B*S, NH, 64] row-major. mul = HD^-0.5 for q, 1.0 for k.
// ---------------------------------------------------------------------------
__global__ __launch_bounds__(256) void rms_rope(
    float* __restrict__ t, const float* __restrict__ cosp,
    const float* __restrict__ sinp, const float* __restrict__ scale,
    int NH, float mul)
{
    const int warp = (blockIdx.x * blockDim.x + threadIdx.x) >> 5;
    const int lane = threadIdx.x & 31;
    const int s = (warp / NH) % S_;
    float* p = t + (size_t)warp * HD_;

    float t1 = p[lane];
    float t2 = p[lane + 32];
    float ss = t1 * t1 + t2 * t2;
    #pragma unroll
    for (int o = 16; o > 0; o >>= 1) ss += __shfl_xor_sync(0xffffffffu, ss, o);
    float rs = rsqrtf(ss * (1.0f / HD_) + 1e-6f);

    float n1 = t1 * rs * (1.0f + scale[lane]);
    float n2 = t2 * rs * (1.0f + scale[lane + 32]);

    float c1 = cosp[s * HD_ + lane],      c2 = cosp[s * HD_ + lane + 32];
    float s1 = sinp[s * HD_ + lane],      s2 = sinp[s * HD_ + lane + 32];
    // rotated = concat(-t2, t1)
    float o1 = (n1 * c1 - n2 * s1) * mul;
    float o2 = (n2 * c2 + n1 * s2) * mul;
    p[lane]      = o1;
    p[lane + 32] = o2;
}

// ---------------------------------------------------------------------------
// Causal flash attention (fp32). Block = one (b, h, 64-query tile). 128 threads.
// Key tiles of 32. Online softmax, ctx accumulated in registers (4 rows x 8 dims).
// q: [B*S, H, 64], k/v: [B*S, G, 64], ctx: [B*S, H, 64]
// ---------------------------------------------------------------------------
#define NEG_BIG (-1e30f)

__global__ __launch_bounds__(128) void attn_kernel(
    const float* __restrict__ q, const float* __restrict__ k,
    const float* __restrict__ v, float* __restrict__ ctx)
{
    __shared__ __align__(16) float Qs[64][64];  // [d][qrow]
    __shared__ __align__(16) float Ks[64][32];  // [d][key]
    __shared__ __align__(16) float Vs[32][64];  // [key][d]
    __shared__ __align__(16) float Ps[32][64];  // [key][qrow]
    __shared__ float mS[64], lS[64], aS[64];

    const int tid = threadIdx.x;
    const int qt  = blockIdx.x;
    const int h   = blockIdx.y;
    const int b   = blockIdx.z;
    const int g   = h / GS_;
    const int q0  = qt * 64;
    const int ty  = tid >> 3;   // 0..15 -> q rows ty*4 .. ty*4+3
    const int tx  = tid & 7;    // 0..7  -> (keys tx*4..) / (dims tx*8..)

    // Load Q tile transposed
    for (int i = tid; i < 64 * 16; i += 128) {
        int r = i >> 4, d4 = (i & 15) << 2;
        float4 val = *(const float4*)(q + (((size_t)(b * S_ + q0 + r)) * H_ + h) * HD_ + d4);
        Qs[d4+0][r] = val.x; Qs[d4+1][r] = val.y;
        Qs[d4+2][r] = val.z; Qs[d4+3][r] = val.w;
    }
    if (tid < 64) { mS[tid] = NEG_BIG; lS[tid] = 0.f; }

    float acc[4][8];
    #pragma unroll
    for (int i = 0; i < 4; i++)
        #pragma unroll
        for (int j = 0; j < 8; j++) acc[i][j] = 0.f;

    __syncthreads();

    const int kend = q0 + 64;
    for (int kt0 = 0; kt0 < kend; kt0 += 32) {
        // Load K tile transposed + V tile
        for (int i = tid; i < 32 * 16; i += 128) {
            int r = i >> 4, d4 = (i & 15) << 2;
            size_t base = (((size_t)(b * S_ + kt0 + r)) * G_ + g) * HD_;
            float4 kv = *(const float4*)(k + base + d4);
            Ks[d4+0][r] = kv.x; Ks[d4+1][r] = kv.y;
            Ks[d4+2][r] = kv.z; Ks[d4+3][r] = kv.w;
            *(float4*)&Vs[r][d4] = *(const float4*)(v + base + d4);
        }
        __syncthreads();

        // Scores: rows ty*4+i, keys tx*4+j
        float sc[4][4];
        #pragma unroll
        for (int i = 0; i < 4; i++)
            #pragma unroll
            for (int j = 0; j < 4; j++) sc[i][j] = 0.f;

        #pragma unroll
        for (int d = 0; d < 64; d++) {
            float4 qa = *(const float4*)&Qs[d][ty * 4];
            float4 kb = *(const float4*)&Ks[d][tx * 4];
            float a[4] = {qa.x, qa.y, qa.z, qa.w};
            float bb[4] = {kb.x, kb.y, kb.z, kb.w};
            #pragma unroll
            for (int i = 0; i < 4; i++)
                #pragma unroll
                for (int j = 0; j < 4; j++)
                    sc[i][j] = fmaf(a[i], bb[j], sc[i][j]);
        }

        // Causal mask, write transposed raw scores
        #pragma unroll
        for (int i = 0; i < 4; i++) {
            int qi = q0 + ty * 4 + i;
            #pragma unroll
            for (int j = 0; j < 4; j++) {
                int kj = kt0 + tx * 4 + j;
                Ps[tx * 4 + j][ty * 4 + i] = (kj > qi) ? NEG_BIG : sc[i][j];
            }
        }
        __syncthreads();

        // Online softmax: one thread per q row
        if (tid < 64) {
            float m_old = mS[tid];
            float mx = m_old;
            #pragma unroll
            for (int t = 0; t < 32; t++) mx = fmaxf(mx, Ps[t][tid]);
            float alpha = __expf(m_old - mx);
            float sum = 0.f;
            #pragma unroll
            for (int t = 0; t < 32; t++) {
                float pv = __expf(Ps[t][tid] - mx);
                Ps[t][tid] = pv;
                sum += pv;
            }
            mS[tid] = mx;
            lS[tid] = lS[tid] * alpha + sum;
            aS[tid] = alpha;
        }
        __syncthreads();

        // Rescale accumulators + P@V
        #pragma unroll
        for (int i = 0; i < 4; i++) {
            float a = aS[ty * 4 + i];
            #pragma unroll
            for (int j = 0; j < 8; j++) acc[i][j] *= a;
        }
        #pragma unroll
        for (int t = 0; t < 32; t++) {
            float4 p4 = *(const float4*)&Ps[t][ty * 4];
            float4 v0 = *(const float4*)&Vs[t][tx * 8];
            float4 v1 = *(const float4*)&Vs[t][tx * 8 + 4];
            float pp[4] = {p4.x, p4.y, p4.z, p4.w};
            float vv[8] = {v0.x, v0.y, v0.z, v0.w, v1.x, v1.y, v1.z, v1.w};
            #pragma unroll
            for (int i = 0; i < 4; i++)
                #pragma unroll
                for (int j = 0; j < 8; j++)
                    acc[i][j] = fmaf(pp[i], vv[j], acc[i][j]);
        }
        __syncthreads();
    }

    // Final normalize + write ctx
    #pragma unroll
    for (int i = 0; i < 4; i++) {
        int qi = q0 + ty * 4 + i;
        float inv = 1.0f / lS[ty * 4 + i];
        float* dst = ctx + (((size_t)(b * S_ + qi)) * H_ + h) * HD_ + tx * 8;
        float4 o0 = make_float4(acc[i][0]*inv, acc[i][1]*inv, acc[i][2]*inv, acc[i][3]*inv);
        float4 o1 = make_float4(acc[i][4]*inv, acc[i][5]*inv, acc[i][6]*inv, acc[i][7]*inv);
        *(float4*)(dst)     = o0;
        *(float4*)(dst + 4) = o1;
    }
}

// ---------------------------------------------------------------------------
// Launch
// ---------------------------------------------------------------------------
extern "C" void kernel_launch(void* const* d_in, const int* in_sizes, int n_in,
                              void* d_out, int out_size)
{
    (void)in_sizes; (void)n_in; (void)out_size;
    const float* x    = (const float*)d_in[0];
    // d_in[1] = mask (bool) — causal structure known, unused
    const float* cosp = (const float*)d_in[2];
    const float* sinp = (const float*)d_in[3];
    const float* Wq   = (const float*)d_in[4];
    const float* Wk   = (const float*)d_in[5];
    const float* Wv   = (const float*)d_in[6];
    const float* Wo   = (const float*)d_in[7];
    const float* qsc  = (const float*)d_in[8];
    const float* ksc  = (const float*)d_in[9];
    float* out = (float*)d_out;

    float *pq, *pk, *pv, *pc;
    cudaGetSymbolAddress((void**)&pq, g_q);
    cudaGetSymbolAddress((void**)&pk, g_k);
    cudaGetSymbolAddress((void**)&pv, g_v);
    cudaGetSymbolAddress((void**)&pc, g_ctx);

    const int M = B_ * S_;  // 4096

    // QKV projections
    gemm_nt<<<dim3((H_*HD_)/GBN, M/GBM), 256>>>(x, Wq, pq, M, H_*HD_, D_);
    gemm_nt<<<dim3((G_*HD_)/GBN, M/GBM), 256>>>(x, Wk, pk, M, G_*HD_, D_);
    gemm_nt<<<dim3((G_*HD_)/GBN, M/GBM), 256>>>(x, Wv, pv, M, G_*HD_, D_);

    // RMSNorm + RoPE (+ q * HD^-0.5 = 0.125)
    rms_rope<<<(M * H_) / 8, 256>>>(pq, cosp, sinp, qsc, H_, 0.125f);
    rms_rope<<<(M * G_) / 8, 256>>>(pk, cosp, sinp, ksc, G_, 1.0f);

    // Causal flash attention
    attn_kernel<<<dim3(S_/64, H_, B_), 128>>>(pq, pk, pv, pc);

    // Output projection
    gemm_nt<<<dim3(D_/GBN, M/GBM), 256>>>(pc, Wo, out, M, D_, H_*HD_);
}

// round 2
// speedup vs baseline: 1.0178x; 1.0178x over previous
#include <cuda_runtime.h>
#include <math.h>

#define B_ 2
#define S_ 2048
#define D_ 2048
#define H_ 32
#define G_ 8
#define HD_ 64
#define GS_ (H_/G_)

typedef unsigned long long ull;

// ---- packed f32x2 helpers (sm_103a FFMA2 path; ptxas never auto-fuses) ----
__device__ __forceinline__ ull pk2(float lo, float hi) {
    ull r; asm("mov.b64 %0,{%1,%2};" : "=l"(r) : "f"(lo), "f"(hi)); return r;
}
__device__ __forceinline__ ull bc2(float v) { return pk2(v, v); }
__device__ __forceinline__ void fma2(ull &d, ull a, ull b) {
    asm("fma.rn.f32x2 %0,%1,%2,%0;" : "+l"(d) : "l"(a), "l"(b));
}
__device__ __forceinline__ void mul2(ull &d, ull a) {
    asm("mul.rn.f32x2 %0,%0,%1;" : "+l"(d) : "l"(a));
}
__device__ __forceinline__ void upk2(ull v, float &lo, float &hi) {
    asm("mov.b64 {%0,%1},%2;" : "=f"(lo), "=f"(hi) : "l"(v));
}

// Scratch (device globals: no allocations allowed)
__device__ float g_q[(size_t)B_*S_*H_*HD_];
__device__ float g_k[(size_t)B_*S_*G_*HD_];
__device__ float g_v[(size_t)B_*S_*G_*HD_];
__device__ float g_ctx[(size_t)B_*S_*H_*HD_];

// ---------------------------------------------------------------------------
// NT GEMM: C[M,N] = A[M,K] @ B[N,K]^T, tile 128x64x16, 256 threads.
// Inner loop uses packed fma.rn.f32x2: accumulators are row-pairs.
// ---------------------------------------------------------------------------
#define GBM 128
#define GBN 64
#define GBK 16

__global__ __launch_bounds__(256) void gemm_nt(
    const float* __restrict__ A, const float* __restrict__ Bm,
    float* __restrict__ C, int M, int N, int K)
{
    __shared__ __align__(16) float As[GBK][GBM];
    __shared__ __align__(16) float Bs[GBK][GBN];

    const int tid = threadIdx.x;
    const int m0  = blockIdx.y * GBM;
    const int n0  = blockIdx.x * GBN;
    const int rg  = tid >> 4;   // rows rg*8 .. rg*8+7
    const int cg  = tid & 15;   // cols cg*4 .. cg*4+3

    // acc2[i2][j]: packed rows (rg*8+2*i2, rg*8+2*i2+1), col cg*4+j
    ull acc2[4][4];
    #pragma unroll
    for (int i = 0; i < 4; i++)
        #pragma unroll
        for (int j = 0; j < 4; j++) acc2[i][j] = 0ull;

    for (int kb = 0; kb < K; kb += GBK) {
        #pragma unroll
        for (int f = tid; f < 512; f += 256) {
            int row = f >> 2, kk = (f & 3) << 2;
            float4 v = *(const float4*)(A + (size_t)(m0 + row) * K + kb + kk);
            As[kk+0][row] = v.x; As[kk+1][row] = v.y;
            As[kk+2][row] = v.z; As[kk+3][row] = v.w;
        }
        {
            int row = tid >> 2, kk = (tid & 3) << 2;
            float4 v = *(const float4*)(Bm + (size_t)(n0 + row) * K + kb + kk);
            Bs[kk+0][row] = v.x; Bs[kk+1][row] = v.y;
            Bs[kk+2][row] = v.z; Bs[kk+3][row] = v.w;
        }
        __syncthreads();

        #pragma unroll
        for (int k = 0; k < GBK; k++) {
            float4 a0 = *(const float4*)&As[k][rg * 8];
            float4 a1 = *(const float4*)&As[k][rg * 8 + 4];
            float4 b0 = *(const float4*)&Bs[k][cg * 4];
            ull ap[4] = {pk2(a0.x, a0.y), pk2(a0.z, a0.w),
                         pk2(a1.x, a1.y), pk2(a1.z, a1.w)};
            ull bb[4] = {bc2(b0.x), bc2(b0.y), bc2(b0.z), bc2(b0.w)};
            #pragma unroll
            for (int i = 0; i < 4; i++)
                #pragma unroll
                for (int j = 0; j < 4; j++)
                    fma2(acc2[i][j], ap[i], bb[j]);
        }
        __syncthreads();
    }

    #pragma unroll
    for (int i2 = 0; i2 < 4; i2++) {
        float lo[4], hi[4];
        #pragma unroll
        for (int j = 0; j < 4; j++) upk2(acc2[i2][j], lo[j], hi[j]);
        float4 o0 = make_float4(lo[0], lo[1], lo[2], lo[3]);
        float4 o1 = make_float4(hi[0], hi[1], hi[2], hi[3]);
        *(float4*)(C + (size_t)(m0 + rg * 8 + 2 * i2)     * N + n0 + cg * 4) = o0;
        *(float4*)(C + (size_t)(m0 + rg * 8 + 2 * i2 + 1) * N + n0 + cg * 4) = o1;
    }
}

// ---------------------------------------------------------------------------
// Fused RMSNorm + RoPE + scalar multiply. One warp per row of 64.
// ---------------------------------------------------------------------------
__global__ __launch_bounds__(256) void rms_rope(
    float* __restrict__ t, const float* __restrict__ cosp,
    const float* __restrict__ sinp, const float* __restrict__ scale,
    int NH, float mul)
{
    const int warp = (blockIdx.x * blockDim.x + threadIdx.x) >> 5;
    const int lane = threadIdx.x & 31;
    const int s = (warp / NH) % S_;
    float* p = t + (size_t)warp * HD_;

    float t1 = p[lane];
    float t2 = p[lane + 32];
    float ss = t1 * t1 + t2 * t2;
    #pragma unroll
    for (int o = 16; o > 0; o >>= 1) ss += __shfl_xor_sync(0xffffffffu, ss, o);
    float rs = rsqrtf(ss * (1.0f / HD_) + 1e-6f);

    float n1 = t1 * rs * (1.0f + scale[lane]);
    float n2 = t2 * rs * (1.0f + scale[lane + 32]);

    float c1 = cosp[s * HD_ + lane],      c2 = cosp[s * HD_ + lane + 32];
    float s1 = sinp[s * HD_ + lane],      s2 = sinp[s * HD_ + lane + 32];
    float o1 = (n1 * c1 - n2 * s1) * mul;
    float o2 = (n2 * c2 + n1 * s2) * mul;
    p[lane]      = o1;
    p[lane + 32] = o2;
}

// ---------------------------------------------------------------------------
// Causal flash attention (fp32, packed f32x2 inner loops).
// Block = one (b, h, 64-query tile). 128 threads. Key tiles of 32.
// ---------------------------------------------------------------------------
#define NEG_BIG (-1e30f)

__global__ __launch_bounds__(128) void attn_kernel(
    const float* __restrict__ q, const float* __restrict__ k,
    const float* __restrict__ v, float* __restrict__ ctx)
{
    __shared__ __align__(16) float Qs[64][64];  // [d][qrow]
    __shared__ __align__(16) float Ks[64][32];  // [d][key]
    __shared__ __align__(16) float Vs[32][64];  // [key][d]
    __shared__ __align__(16) float Ps[32][64];  // [key][qrow]
    __shared__ float mS[64], lS[64], aS[64];

    const int tid = threadIdx.x;
    const int qt  = blockIdx.x;
    const int h   = blockIdx.y;
    const int b   = blockIdx.z;
    const int g   = h / GS_;
    const int q0  = qt * 64;
    const int ty  = tid >> 3;   // q rows ty*4 .. ty*4+3
    const int tx  = tid & 7;    // keys tx*4.. / dims tx*8..

    for (int i = tid; i < 64 * 16; i += 128) {
        int r = i >> 4, d4 = (i & 15) << 2;
        float4 val = *(const float4*)(q + (((size_t)(b * S_ + q0 + r)) * H_ + h) * HD_ + d4);
        Qs[d4+0][r] = val.x; Qs[d4+1][r] = val.y;
        Qs[d4+2][r] = val.z; Qs[d4+3][r] = val.w;
    }
    if (tid < 64) { mS[tid] = NEG_BIG; lS[tid] = 0.f; }

    // acc2[i][j2]: q-row ty*4+i, packed dims (tx*8+2*j2, tx*8+2*j2+1)
    ull acc2[4][4];
    #pragma unroll
    for (int i = 0; i < 4; i++)
        #pragma unroll
        for (int j = 0; j < 4; j++) acc2[i][j] = 0ull;

    __syncthreads();

    const int kend = q0 + 64;
    for (int kt0 = 0; kt0 < kend; kt0 += 32) {
        for (int i = tid; i < 32 * 16; i += 128) {
            int r = i >> 4, d4 = (i & 15) << 2;
            size_t base = (((size_t)(b * S_ + kt0 + r)) * G_ + g) * HD_;
            float4 kv = *(const float4*)(k + base + d4);
            Ks[d4+0][r] = kv.x; Ks[d4+1][r] = kv.y;
            Ks[d4+2][r] = kv.z; Ks[d4+3][r] = kv.w;
            *(float4*)&Vs[r][d4] = *(const float4*)(v + base + d4);
        }
        __syncthreads();

        // Scores: packed q-row pairs x 4 keys
        ull sc2[2][4];
        #pragma unroll
        for (int i = 0; i < 2; i++)
            #pragma unroll
            for (int j = 0; j < 4; j++) sc2[i][j] = 0ull;

        #pragma unroll
        for (int d = 0; d < 64; d++) {
            float4 qa = *(const float4*)&Qs[d][ty * 4];
            float4 kb = *(const float4*)&Ks[d][tx * 4];
            ull qp[2] = {pk2(qa.x, qa.y), pk2(qa.z, qa.w)};
            ull bb[4] = {bc2(kb.x), bc2(kb.y), bc2(kb.z), bc2(kb.w)};
            #pragma unroll
            for (int i = 0; i < 2; i++)
                #pragma unroll
                for (int j = 0; j < 4; j++)
                    fma2(sc2[i][j], qp[i], bb[j]);
        }

        // Unpack, causal mask, write transposed raw scores
        #pragma unroll
        for (int i2 = 0; i2 < 2; i2++) {
            float lo[4], hi[4];
            #pragma unroll
            for (int j = 0; j < 4; j++) upk2(sc2[i2][j], lo[j], hi[j]);
            int qi0 = q0 + ty * 4 + 2 * i2;
            #pragma unroll
            for (int j = 0; j < 4; j++) {
                int kj = kt0 + tx * 4 + j;
                Ps[tx * 4 + j][ty * 4 + 2 * i2]     = (kj > qi0)     ? NEG_BIG : lo[j];
                Ps[tx * 4 + j][ty * 4 + 2 * i2 + 1] = (kj > qi0 + 1) ? NEG_BIG : hi[j];
            }
        }
        __syncthreads();

        // Online softmax: one thread per q row
        if (tid < 64) {
            float m_old = mS[tid];
            float mx = m_old;
            #pragma unroll
            for (int t = 0; t < 32; t++) mx = fmaxf(mx, Ps[t][tid]);
            float alpha = __expf(m_old - mx);
            float sum = 0.f;
            #pragma unroll
            for (int t = 0; t < 32; t++) {
                float pv = __expf(Ps[t][tid] - mx);
                Ps[t][tid] = pv;
                sum += pv;
            }
            mS[tid] = mx;
            lS[tid] = lS[tid] * alpha + sum;
            aS[tid] = alpha;
        }
        __syncthreads();

        // Rescale accumulators (packed) + P@V (packed over dims)
        #pragma unroll
        for (int i = 0; i < 4; i++) {
            ull a = bc2(aS[ty * 4 + i]);
            #pragma unroll
            for (int j = 0; j < 4; j++) mul2(acc2[i][j], a);
        }
        #pragma unroll
        for (int t = 0; t < 32; t++) {
            float4 p4 = *(const float4*)&Ps[t][ty * 4];
            float4 v0 = *(const float4*)&Vs[t][tx * 8];
            float4 v1 = *(const float4*)&Vs[t][tx * 8 + 4];
            ull pp[4] = {bc2(p4.x), bc2(p4.y), bc2(p4.z), bc2(p4.w)};
            ull vp[4] = {pk2(v0.x, v0.y), pk2(v0.z, v0.w),
                         pk2(v1.x, v1.y), pk2(v1.z, v1.w)};
            #pragma unroll
            for (int i = 0; i < 4; i++)
                #pragma unroll
                for (int j = 0; j < 4; j++)
                    fma2(acc2[i][j], pp[i], vp[j]);
        }
        __syncthreads();
    }

    // Final normalize + write ctx
    #pragma unroll
    for (int i = 0; i < 4; i++) {
        int qi = q0 + ty * 4 + i;
        float inv = 1.0f / lS[ty * 4 + i];
        float* dst = ctx + (((size_t)(b * S_ + qi)) * H_ + h) * HD_ + tx * 8;
        float lo[4], hi[4];
        #pragma unroll
        for (int j = 0; j < 4; j++) upk2(acc2[i][j], lo[j], hi[j]);
        float4 o0 = make_float4(lo[0]*inv, hi[0]*inv, lo[1]*inv, hi[1]*inv);
        float4 o1 = make_float4(lo[2]*inv, hi[2]*inv, lo[3]*inv, hi[3]*inv);
        *(float4*)(dst)     = o0;
        *(float4*)(dst + 4) = o1;
    }
}

// ---------------------------------------------------------------------------
// Launch
// ---------------------------------------------------------------------------
extern "C" void kernel_launch(void* const* d_in, const int* in_sizes, int n_in,
                              void* d_out, int out_size)
{
    (void)in_sizes; (void)n_in; (void)out_size;
    const float* x    = (const float*)d_in[0];
    const float* cosp = (const float*)d_in[2];
    const float* sinp = (const float*)d_in[3];
    const float* Wq   = (const float*)d_in[4];
    const float* Wk   = (const float*)d_in[5];
    const float* Wv   = (const float*)d_in[6];
    const float* Wo   = (const float*)d_in[7];
    const float* qsc  = (const float*)d_in[8];
    const float* ksc  = (const float*)d_in[9];
    float* out = (float*)d_out;

    float *pq, *pk, *pv, *pc;
    cudaGetSymbolAddress((void**)&pq, g_q);
    cudaGetSymbolAddress((void**)&pk, g_k);
    cudaGetSymbolAddress((void**)&pv, g_v);
    cudaGetSymbolAddress((void**)&pc, g_ctx);

    const int M = B_ * S_;  // 4096

    gemm_nt<<<dim3((H_*HD_)/GBN, M/GBM), 256>>>(x, Wq, pq, M, H_*HD_, D_);
    gemm_nt<<<dim3((G_*HD_)/GBN, M/GBM), 256>>>(x, Wk, pk, M, G_*HD_, D_);
    gemm_nt<<<dim3((G_*HD_)/GBN, M/GBM), 256>>>(x, Wv, pv, M, G_*HD_, D_);

    rms_rope<<<(M * H_) / 8, 256>>>(pq, cosp, sinp, qsc, H_, 0.125f);
    rms_rope<<<(M * G_) / 8, 256>>>(pk, cosp, sinp, ksc, G_, 1.0f);

    attn_kernel<<<dim3(S_/64, H_, B_), 128>>>(pq, pk, pv, pc);

    gemm_nt<<<dim3(D_/GBN, M/GBM), 256>>>(pc, Wo, out, M, D_, H_*HD_);
}

// round 3
// speedup vs baseline: 1.5877x; 1.5599x over previous
#include <cuda_runtime.h>
#include <cuda_bf16.h>
#include <math.h>

#define B_ 2
#define S_ 2048
#define D_ 2048
#define H_ 32
#define G_ 8
#define HD_ 64
#define GS_ (H_/G_)

typedef unsigned long long ull;
typedef unsigned int uint32;

// ---- packed f32x2 helpers (kept for attention) ----
__device__ __forceinline__ ull pk2(float lo, float hi) {
    ull r; asm("mov.b64 %0,{%1,%2};" : "=l"(r) : "f"(lo), "f"(hi)); return r;
}
__device__ __forceinline__ ull bc2(float v) { return pk2(v, v); }
__device__ __forceinline__ void fma2(ull &d, ull a, ull b) {
    asm("fma.rn.f32x2 %0,%1,%2,%0;" : "+l"(d) : "l"(a), "l"(b));
}
__device__ __forceinline__ void mul2(ull &d, ull a) {
    asm("mul.rn.f32x2 %0,%0,%1;" : "+l"(d) : "l"(a));
}
__device__ __forceinline__ void upk2(ull v, float &lo, float &hi) {
    asm("mov.b64 {%0,%1},%2;" : "=f"(lo), "=f"(hi) : "l"(v));
}

// ---- tensor-core helpers ----
__device__ __forceinline__ void ldsm4(uint32 &r0, uint32 &r1, uint32 &r2, uint32 &r3,
                                      const void* p) {
    uint32 a = (uint32)__cvta_generic_to_shared(p);
    asm volatile("ldmatrix.sync.aligned.m8n8.x4.shared.b16 {%0,%1,%2,%3},[%4];"
                 : "=r"(r0), "=r"(r1), "=r"(r2), "=r"(r3) : "r"(a));
}
__device__ __forceinline__ void mma16816(float c[4], const uint32 a[4],
                                         uint32 b0, uint32 b1) {
    asm volatile(
        "mma.sync.aligned.m16n8k16.row.col.f32.bf16.bf16.f32 "
        "{%0,%1,%2,%3},{%4,%5,%6,%7},{%8,%9},{%0,%1,%2,%3};"
        : "+f"(c[0]), "+f"(c[1]), "+f"(c[2]), "+f"(c[3])
        : "r"(a[0]), "r"(a[1]), "r"(a[2]), "r"(a[3]), "r"(b0), "r"(b1));
}
__device__ __forceinline__ uint32 pkbf2(__nv_bfloat16 a, __nv_bfloat16 b) {
    unsigned short ua = *(unsigned short*)&a, ub = *(unsigned short*)&b;
    return (uint32)ua | ((uint32)ub << 16);
}
__device__ __forceinline__ void cvt4(float4 v, uint2 &hi, uint2 &lo) {
    __nv_bfloat16 h0 = __float2bfloat16(v.x);
    __nv_bfloat16 h1 = __float2bfloat16(v.y);
    __nv_bfloat16 h2 = __float2bfloat16(v.z);
    __nv_bfloat16 h3 = __float2bfloat16(v.w);
    __nv_bfloat16 l0 = __float2bfloat16(v.x - __bfloat162float(h0));
    __nv_bfloat16 l1 = __float2bfloat16(v.y - __bfloat162float(h1));
    __nv_bfloat16 l2 = __float2bfloat16(v.z - __bfloat162float(h2));
    __nv_bfloat16 l3 = __float2bfloat16(v.w - __bfloat162float(h3));
    hi = make_uint2(pkbf2(h0, h1), pkbf2(h2, h3));
    lo = make_uint2(pkbf2(l0, l1), pkbf2(l2, l3));
}

// Scratch
__device__ float g_q[(size_t)B_*S_*H_*HD_];
__device__ float g_k[(size_t)B_*S_*G_*HD_];
__device__ float g_v[(size_t)B_*S_*G_*HD_];
__device__ float g_ctx[(size_t)B_*S_*H_*HD_];

// ---------------------------------------------------------------------------
// NT GEMM via bf16-split tensor cores: C[M,N] = A[M,K] @ B[N,K]^T (fp32 io).
// CTA tile 128x64x32, 256 threads, warp tile 32x32.
// a = a_hi + a_lo (bf16); C += Ah*Bh + Ah*Bl + Al*Bh  (fp32 accum).
// ---------------------------------------------------------------------------
#define BM 128
#define BN 64
#define BKK 32
#define ASTR 40   // bf16 elems per smem row: 32 + 8 pad (conflict-free ldmatrix)

__global__ __launch_bounds__(256) void gemm_nt_tc(
    const float* __restrict__ A, const float* __restrict__ Bm,
    float* __restrict__ C, int M, int N, int K)
{
    __shared__ __align__(16) __nv_bfloat16 Ah[BM*ASTR];
    __shared__ __align__(16) __nv_bfloat16 Al[BM*ASTR];
    __shared__ __align__(16) __nv_bfloat16 Bh[BN*ASTR];
    __shared__ __align__(16) __nv_bfloat16 Bl[BN*ASTR];

    const int tid  = threadIdx.x;
    const int lane = tid & 31;
    const int warp = tid >> 5;
    const int m0 = blockIdx.y * BM;
    const int n0 = blockIdx.x * BN;
    const int wm = (warp >> 1) * 32;   // 4 warps along M
    const int wn = (warp & 1) * 32;    // 2 warps along N

    // ldmatrix lane address components
    const int a_lr = lane & 15;
    const int a_k8 = ((lane >> 4) & 1) << 3;
    const int b_nr = (((lane >> 4) & 1) << 3) | (lane & 7);
    const int b_k8 = ((lane >> 3) & 1) << 3;

    float acc[2][4][4];
    #pragma unroll
    for (int i = 0; i < 2; i++)
        #pragma unroll
        for (int j = 0; j < 4; j++)
            #pragma unroll
            for (int t = 0; t < 4; t++) acc[i][j][t] = 0.f;

    float4 ar[4], br[2];
    // prefetch first stage
    #pragma unroll
    for (int it = 0; it < 4; it++) {
        int f = it * 256 + tid, row = f >> 3, c4 = f & 7;
        ar[it] = *(const float4*)(A + (size_t)(m0 + row) * K + c4 * 4);
    }
    #pragma unroll
    for (int it = 0; it < 2; it++) {
        int f = it * 256 + tid, row = f >> 3, c4 = f & 7;
        br[it] = *(const float4*)(Bm + (size_t)(n0 + row) * K + c4 * 4);
    }

    for (int kb = 0; kb < K; kb += BKK) {
        // store staged data to smem (fp32 -> bf16 hi/lo)
        #pragma unroll
        for (int it = 0; it < 4; it++) {
            int f = it * 256 + tid, row = f >> 3, c4 = f & 7;
            uint2 hi, lo; cvt4(ar[it], hi, lo);
            *(uint2*)&Ah[row * ASTR + c4 * 4] = hi;
            *(uint2*)&Al[row * ASTR + c4 * 4] = lo;
        }
        #pragma unroll
        for (int it = 0; it < 2; it++) {
            int f = it * 256 + tid, row = f >> 3, c4 = f & 7;
            uint2 hi, lo; cvt4(br[it], hi, lo);
            *(uint2*)&Bh[row * ASTR + c4 * 4] = hi;
            *(uint2*)&Bl[row * ASTR + c4 * 4] = lo;
        }
        __syncthreads();

        // prefetch next stage (overlaps with MMA below)
        if (kb + BKK < K) {
            #pragma unroll
            for (int it = 0; it < 4; it++) {
                int f = it * 256 + tid, row = f >> 3, c4 = f & 7;
                ar[it] = *(const float4*)(A + (size_t)(m0 + row) * K + kb + BKK + c4 * 4);
            }
            #pragma unroll
            for (int it = 0; it < 2; it++) {
                int f = it * 256 + tid, row = f >> 3, c4 = f & 7;
                br[it] = *(const float4*)(Bm + (size_t)(n0 + row) * K + kb + BKK + c4 * 4);
            }
        }

        #pragma unroll
        for (int ks = 0; ks < BKK; ks += 16) {
            uint32 ah[2][4], al[2][4], bh[2][4], bl[2][4];
            #pragma unroll
            for (int mi = 0; mi < 2; mi++) {
                int off = (wm + mi * 16 + a_lr) * ASTR + ks + a_k8;
                ldsm4(ah[mi][0], ah[mi][1], ah[mi][2], ah[mi][3], &Ah[off]);
                ldsm4(al[mi][0], al[mi][1], al[mi][2], al[mi][3], &Al[off]);
            }
            #pragma unroll
            for (int p = 0; p < 2; p++) {
                int off = (wn + p * 16 + b_nr) * ASTR + ks + b_k8;
                ldsm4(bh[p][0], bh[p][1], bh[p][2], bh[p][3], &Bh[off]);
                ldsm4(bl[p][0], bl[p][1], bl[p][2], bl[p][3], &Bl[off]);
            }
            #pragma unroll
            for (int mi = 0; mi < 2; mi++)
                #pragma unroll
                for (int ni = 0; ni < 4; ni++) {
                    int p = ni >> 1, s = (ni & 1) * 2;
                    mma16816(acc[mi][ni], ah[mi], bh[p][s], bh[p][s+1]);
                    mma16816(acc[mi][ni], ah[mi], bl[p][s], bl[p][s+1]);
                    mma16816(acc[mi][ni], al[mi], bh[p][s], bh[p][s+1]);
                }
        }
        __syncthreads();
    }

    // epilogue
    const int g = lane >> 2, t = lane & 3;
    #pragma unroll
    for (int mi = 0; mi < 2; mi++)
        #pragma unroll
        for (int ni = 0; ni < 4; ni++) {
            int row = m0 + wm + mi * 16 + g;
            int col = n0 + wn + ni * 8 + t * 2;
            *(float2*)(C + (size_t)row * N + col)       = make_float2(acc[mi][ni][0], acc[mi][ni][1]);
            *(float2*)(C + (size_t)(row + 8) * N + col) = make_float2(acc[mi][ni][2], acc[mi][ni][3]);
        }
}

// ---------------------------------------------------------------------------
// Fused RMSNorm + RoPE + scalar multiply. One warp per row of 64.
// ---------------------------------------------------------------------------
__global__ __launch_bounds__(256) void rms_rope(
    float* __restrict__ t, const float* __restrict__ cosp,
    const float* __restrict__ sinp, const float* __restrict__ scale,
    int NH, float mul)
{
    const int warp = (blockIdx.x * blockDim.x + threadIdx.x) >> 5;
    const int lane = threadIdx.x & 31;
    const int s = (warp / NH) % S_;
    float* p = t + (size_t)warp * HD_;

    float t1 = p[lane];
    float t2 = p[lane + 32];
    float ss = t1 * t1 + t2 * t2;
    #pragma unroll
    for (int o = 16; o > 0; o >>= 1) ss += __shfl_xor_sync(0xffffffffu, ss, o);
    float rs = rsqrtf(ss * (1.0f / HD_) + 1e-6f);

    float n1 = t1 * rs * (1.0f + scale[lane]);
    float n2 = t2 * rs * (1.0f + scale[lane + 32]);

    float c1 = cosp[s * HD_ + lane],      c2 = cosp[s * HD_ + lane + 32];
    float s1 = sinp[s * HD_ + lane],      s2 = sinp[s * HD_ + lane + 32];
    float o1 = (n1 * c1 - n2 * s1) * mul;
    float o2 = (n2 * c2 + n1 * s2) * mul;
    p[lane]      = o1;
    p[lane + 32] = o2;
}

// ---------------------------------------------------------------------------
// Causal flash attention (fp32, packed f32x2 inner loops). Unchanged from R2.
// ---------------------------------------------------------------------------
#define NEG_BIG (-1e30f)

__global__ __launch_bounds__(128) void attn_kernel(
    const float* __restrict__ q, const float* __restrict__ k,
    const float* __restrict__ v, float* __restrict__ ctx)
{
    __shared__ __align__(16) float Qs[64][64];
    __shared__ __align__(16) float Ks[64][32];
    __shared__ __align__(16) float Vs[32][64];
    __shared__ __align__(16) float Ps[32][64];
    __shared__ float mS[64], lS[64], aS[64];

    const int tid = threadIdx.x;
    const int qt  = blockIdx.x;
    const int h   = blockIdx.y;
    const int b   = blockIdx.z;
    const int g   = h / GS_;
    const int q0  = qt * 64;
    const int ty  = tid >> 3;
    const int tx  = tid & 7;

    for (int i = tid; i < 64 * 16; i += 128) {
        int r = i >> 4, d4 = (i & 15) << 2;
        float4 val = *(const float4*)(q + (((size_t)(b * S_ + q0 + r)) * H_ + h) * HD_ + d4);
        Qs[d4+0][r] = val.x; Qs[d4+1][r] = val.y;
        Qs[d4+2][r] = val.z; Qs[d4+3][r] = val.w;
    }
    if (tid < 64) { mS[tid] = NEG_BIG; lS[tid] = 0.f; }

    ull acc2[4][4];
    #pragma unroll
    for (int i = 0; i < 4; i++)
        #pragma unroll
        for (int j = 0; j < 4; j++) acc2[i][j] = 0ull;

    __syncthreads();

    const int kend = q0 + 64;
    for (int kt0 = 0; kt0 < kend; kt0 += 32) {
        for (int i = tid; i < 32 * 16; i += 128) {
            int r = i >> 4, d4 = (i & 15) << 2;
            size_t base = (((size_t)(b * S_ + kt0 + r)) * G_ + g) * HD_;
            float4 kv = *(const float4*)(k + base + d4);
            Ks[d4+0][r] = kv.x; Ks[d4+1][r] = kv.y;
            Ks[d4+2][r] = kv.z; Ks[d4+3][r] = kv.w;
            *(float4*)&Vs[r][d4] = *(const float4*)(v + base + d4);
        }
        __syncthreads();

        ull sc2[2][4];
        #pragma unroll
        for (int i = 0; i < 2; i++)
            #pragma unroll
            for (int j = 0; j < 4; j++) sc2[i][j] = 0ull;

        #pragma unroll
        for (int d = 0; d < 64; d++) {
            float4 qa = *(const float4*)&Qs[d][ty * 4];
            float4 kb = *(const float4*)&Ks[d][tx * 4];
            ull qp[2] = {pk2(qa.x, qa.y), pk2(qa.z, qa.w)};
            ull bb[4] = {bc2(kb.x), bc2(kb.y), bc2(kb.z), bc2(kb.w)};
            #pragma unroll
            for (int i = 0; i < 2; i++)
                #pragma unroll
                for (int j = 0; j < 4; j++)
                    fma2(sc2[i][j], qp[i], bb[j]);
        }

        #pragma unroll
        for (int i2 = 0; i2 < 2; i2++) {
            float lo[4], hi[4];
            #pragma unroll
            for (int j = 0; j < 4; j++) upk2(sc2[i2][j], lo[j], hi[j]);
            int qi0 = q0 + ty * 4 + 2 * i2;
            #pragma unroll
            for (int j = 0; j < 4; j++) {
                int kj = kt0 + tx * 4 + j;
                Ps[tx * 4 + j][ty * 4 + 2 * i2]     = (kj > qi0)     ? NEG_BIG : lo[j];
                Ps[tx * 4 + j][ty * 4 + 2 * i2 + 1] = (kj > qi0 + 1) ? NEG_BIG : hi[j];
            }
        }
        __syncthreads();

        if (tid < 64) {
            float m_old = mS[tid];
            float mx = m_old;
            #pragma unroll
            for (int t = 0; t < 32; t++) mx = fmaxf(mx, Ps[t][tid]);
            float alpha = __expf(m_old - mx);
            float sum = 0.f;
            #pragma unroll
            for (int t = 0; t < 32; t++) {
                float pv = __expf(Ps[t][tid] - mx);
                Ps[t][tid] = pv;
                sum += pv;
            }
            mS[tid] = mx;
            lS[tid] = lS[tid] * alpha + sum;
            aS[tid] = alpha;
        }
        __syncthreads();

        #pragma unroll
        for (int i = 0; i < 4; i++) {
            ull a = bc2(aS[ty * 4 + i]);
            #pragma unroll
            for (int j = 0; j < 4; j++) mul2(acc2[i][j], a);
        }
        #pragma unroll
        for (int t = 0; t < 32; t++) {
            float4 p4 = *(const float4*)&Ps[t][ty * 4];
            float4 v0 = *(const float4*)&Vs[t][tx * 8];
            float4 v1 = *(const float4*)&Vs[t][tx * 8 + 4];
            ull pp[4] = {bc2(p4.x), bc2(p4.y), bc2(p4.z), bc2(p4.w)};
            ull vp[4] = {pk2(v0.x, v0.y), pk2(v0.z, v0.w),
                         pk2(v1.x, v1.y), pk2(v1.z, v1.w)};
            #pragma unroll
            for (int i = 0; i < 4; i++)
                #pragma unroll
                for (int j = 0; j < 4; j++)
                    fma2(acc2[i][j], pp[i], vp[j]);
        }
        __syncthreads();
    }

    #pragma unroll
    for (int i = 0; i < 4; i++) {
        int qi = q0 + ty * 4 + i;
        float inv = 1.0f / lS[ty * 4 + i];
        float* dst = ctx + (((size_t)(b * S_ + qi)) * H_ + h) * HD_ + tx * 8;
        float lo[4], hi[4];
        #pragma unroll
        for (int j = 0; j < 4; j++) upk2(acc2[i][j], lo[j], hi[j]);
        float4 o0 = make_float4(lo[0]*inv, hi[0]*inv, lo[1]*inv, hi[1]*inv);
        float4 o1 = make_float4(lo[2]*inv, hi[2]*inv, lo[3]*inv, hi[3]*inv);
        *(float4*)(dst)     = o0;
        *(float4*)(dst + 4) = o1;
    }
}

// ---------------------------------------------------------------------------
// Launch
// ---------------------------------------------------------------------------
extern "C" void kernel_launch(void* const* d_in, const int* in_sizes, int n_in,
                              void* d_out, int out_size)
{
    (void)in_sizes; (void)n_in; (void)out_size;
    const float* x    = (const float*)d_in[0];
    const float* cosp = (const float*)d_in[2];
    const float* sinp = (const float*)d_in[3];
    const float* Wq   = (const float*)d_in[4];
    const float* Wk   = (const float*)d_in[5];
    const float* Wv   = (const float*)d_in[6];
    const float* Wo   = (const float*)d_in[7];
    const float* qsc  = (const float*)d_in[8];
    const float* ksc  = (const float*)d_in[9];
    float* out = (float*)d_out;

    float *pq, *pk, *pv, *pc;
    cudaGetSymbolAddress((void**)&pq, g_q);
    cudaGetSymbolAddress((void**)&pk, g_k);
    cudaGetSymbolAddress((void**)&pv, g_v);
    cudaGetSymbolAddress((void**)&pc, g_ctx);

    const int M = B_ * S_;  // 4096

    gemm_nt_tc<<<dim3((H_*HD_)/BN, M/BM), 256>>>(x, Wq, pq, M, H_*HD_, D_);
    gemm_nt_tc<<<dim3((G_*HD_)/BN, M/BM), 256>>>(x, Wk, pk, M, G_*HD_, D_);
    gemm_nt_tc<<<dim3((G_*HD_)/BN, M/BM), 256>>>(x, Wv, pv, M, G_*HD_, D_);

    rms_rope<<<(M * H_) / 8, 256>>>(pq, cosp, sinp, qsc, H_, 0.125f);
    rms_rope<<<(M * G_) / 8, 256>>>(pk, cosp, sinp, ksc, G_, 1.0f);

    attn_kernel<<<dim3(S_/64, H_, B_), 128>>>(pq, pk, pv, pc);

    gemm_nt_tc<<<dim3(D_/BN, M/BM), 256>>>(pc, Wo, out, M, D_, H_*HD_);
}

// round 4
// speedup vs baseline: 3.3721x; 2.1239x over previous
#include <cuda_runtime.h>
#include <cuda_bf16.h>
#include <math.h>

#define B_ 2
#define S_ 2048
#define D_ 2048
#define H_ 32
#define G_ 8
#define HD_ 64
#define GS_ (H_/G_)

typedef unsigned int uint32;

// ---- tensor-core helpers ----
__device__ __forceinline__ void ldsm4(uint32 &r0, uint32 &r1, uint32 &r2, uint32 &r3,
                                      const void* p) {
    uint32 a = (uint32)__cvta_generic_to_shared(p);
    asm volatile("ldmatrix.sync.aligned.m8n8.x4.shared.b16 {%0,%1,%2,%3},[%4];"
                 : "=r"(r0), "=r"(r1), "=r"(r2), "=r"(r3) : "r"(a));
}
__device__ __forceinline__ void ldsm2t(uint32 &r0, uint32 &r1, const void* p) {
    uint32 a = (uint32)__cvta_generic_to_shared(p);
    asm volatile("ldmatrix.sync.aligned.m8n8.x2.trans.shared.b16 {%0,%1},[%2];"
                 : "=r"(r0), "=r"(r1) : "r"(a));
}
__device__ __forceinline__ void mma16816(float c[4], const uint32 a[4],
                                         uint32 b0, uint32 b1) {
    asm volatile(
        "mma.sync.aligned.m16n8k16.row.col.f32.bf16.bf16.f32 "
        "{%0,%1,%2,%3},{%4,%5,%6,%7},{%8,%9},{%0,%1,%2,%3};"
        : "+f"(c[0]), "+f"(c[1]), "+f"(c[2]), "+f"(c[3])
        : "r"(a[0]), "r"(a[1]), "r"(a[2]), "r"(a[3]), "r"(b0), "r"(b1));
}
// split two fp32 into packed bf16 hi + packed bf16 lo (p0 in low half)
__device__ __forceinline__ void split2(float p0, float p1, uint32 &h, uint32 &l) {
    asm("cvt.rn.bf16x2.f32 %0, %1, %2;" : "=r"(h) : "f"(p1), "f"(p0));
    float r0 = __uint_as_float(h << 16);
    float r1 = __uint_as_float(h & 0xffff0000u);
    asm("cvt.rn.bf16x2.f32 %0, %1, %2;" : "=r"(l) : "f"(p1 - r1), "f"(p0 - r0));
}
__device__ __forceinline__ void cvt4(float4 v, uint2 &hi, uint2 &lo) {
    split2(v.x, v.y, hi.x, lo.x);
    split2(v.z, v.w, hi.y, lo.y);
}

// Scratch
__device__ float g_q[(size_t)B_*S_*H_*HD_];
__device__ float g_k[(size_t)B_*S_*G_*HD_];
__device__ float g_v[(size_t)B_*S_*G_*HD_];
__device__ float g_ctx[(size_t)B_*S_*H_*HD_];

// ---------------------------------------------------------------------------
// NT GEMM via bf16-split tensor cores (validated R3). CTA 128x64x32.
// ---------------------------------------------------------------------------
#define BM 128
#define BN 64
#define BKK 32
#define ASTR 40

__global__ __launch_bounds__(256) void gemm_nt_tc(
    const float* __restrict__ A, const float* __restrict__ Bm,
    float* __restrict__ C, int M, int N, int K)
{
    __shared__ __align__(16) __nv_bfloat16 Ah[BM*ASTR];
    __shared__ __align__(16) __nv_bfloat16 Al[BM*ASTR];
    __shared__ __align__(16) __nv_bfloat16 Bh[BN*ASTR];
    __shared__ __align__(16) __nv_bfloat16 Bl[BN*ASTR];

    const int tid  = threadIdx.x;
    const int lane = tid & 31;
    const int warp = tid >> 5;
    const int m0 = blockIdx.y * BM;
    const int n0 = blockIdx.x * BN;
    const int wm = (warp >> 1) * 32;
    const int wn = (warp & 1) * 32;

    const int a_lr = lane & 15;
    const int a_k8 = ((lane >> 4) & 1) << 3;
    const int b_nr = (((lane >> 4) & 1) << 3) | (lane & 7);
    const int b_k8 = ((lane >> 3) & 1) << 3;

    float acc[2][4][4];
    #pragma unroll
    for (int i = 0; i < 2; i++)
        #pragma unroll
        for (int j = 0; j < 4; j++)
            #pragma unroll
            for (int t = 0; t < 4; t++) acc[i][j][t] = 0.f;

    float4 ar[4], br[2];
    #pragma unroll
    for (int it = 0; it < 4; it++) {
        int f = it * 256 + tid, row = f >> 3, c4 = f & 7;
        ar[it] = *(const float4*)(A + (size_t)(m0 + row) * K + c4 * 4);
    }
    #pragma unroll
    for (int it = 0; it < 2; it++) {
        int f = it * 256 + tid, row = f >> 3, c4 = f & 7;
        br[it] = *(const float4*)(Bm + (size_t)(n0 + row) * K + c4 * 4);
    }

    for (int kb = 0; kb < K; kb += BKK) {
        #pragma unroll
        for (int it = 0; it < 4; it++) {
            int f = it * 256 + tid, row = f >> 3, c4 = f & 7;
            uint2 hi, lo; cvt4(ar[it], hi, lo);
            *(uint2*)&Ah[row * ASTR + c4 * 4] = hi;
            *(uint2*)&Al[row * ASTR + c4 * 4] = lo;
        }
        #pragma unroll
        for (int it = 0; it < 2; it++) {
            int f = it * 256 + tid, row = f >> 3, c4 = f & 7;
            uint2 hi, lo; cvt4(br[it], hi, lo);
            *(uint2*)&Bh[row * ASTR + c4 * 4] = hi;
            *(uint2*)&Bl[row * ASTR + c4 * 4] = lo;
        }
        __syncthreads();

        if (kb + BKK < K) {
            #pragma unroll
            for (int it = 0; it < 4; it++) {
                int f = it * 256 + tid, row = f >> 3, c4 = f & 7;
                ar[it] = *(const float4*)(A + (size_t)(m0 + row) * K + kb + BKK + c4 * 4);
            }
            #pragma unroll
            for (int it = 0; it < 2; it++) {
                int f = it * 256 + tid, row = f >> 3, c4 = f & 7;
                br[it] = *(const float4*)(Bm + (size_t)(n0 + row) * K + kb + BKK + c4 * 4);
            }
        }

        #pragma unroll
        for (int ks = 0; ks < BKK; ks += 16) {
            uint32 ah[2][4], al[2][4], bh[2][4], bl[2][4];
            #pragma unroll
            for (int mi = 0; mi < 2; mi++) {
                int off = (wm + mi * 16 + a_lr) * ASTR + ks + a_k8;
                ldsm4(ah[mi][0], ah[mi][1], ah[mi][2], ah[mi][3], &Ah[off]);
                ldsm4(al[mi][0], al[mi][1], al[mi][2], al[mi][3], &Al[off]);
            }
            #pragma unroll
            for (int p = 0; p < 2; p++) {
                int off = (wn + p * 16 + b_nr) * ASTR + ks + b_k8;
                ldsm4(bh[p][0], bh[p][1], bh[p][2], bh[p][3], &Bh[off]);
                ldsm4(bl[p][0], bl[p][1], bl[p][2], bl[p][3], &Bl[off]);
            }
            #pragma unroll
            for (int mi = 0; mi < 2; mi++)
                #pragma unroll
                for (int ni = 0; ni < 4; ni++) {
                    int p = ni >> 1, s = (ni & 1) * 2;
                    mma16816(acc[mi][ni], ah[mi], bh[p][s], bh[p][s+1]);
                    mma16816(acc[mi][ni], ah[mi], bl[p][s], bl[p][s+1]);
                    mma16816(acc[mi][ni], al[mi], bh[p][s], bh[p][s+1]);
                }
        }
        __syncthreads();
    }

    const int g = lane >> 2, t = lane & 3;
    #pragma unroll
    for (int mi = 0; mi < 2; mi++)
        #pragma unroll
        for (int ni = 0; ni < 4; ni++) {
            int row = m0 + wm + mi * 16 + g;
            int col = n0 + wn + ni * 8 + t * 2;
            *(float2*)(C + (size_t)row * N + col)       = make_float2(acc[mi][ni][0], acc[mi][ni][1]);
            *(float2*)(C + (size_t)(row + 8) * N + col) = make_float2(acc[mi][ni][2], acc[mi][ni][3]);
        }
}

// ---------------------------------------------------------------------------
// Fused RMSNorm + RoPE + scalar multiply. One warp per row of 64.
// ---------------------------------------------------------------------------
__global__ __launch_bounds__(256) void rms_rope(
    float* __restrict__ t, const float* __restrict__ cosp,
    const float* __restrict__ sinp, const float* __restrict__ scale,
    int NH, float mul)
{
    const int warp = (blockIdx.x * blockDim.x + threadIdx.x) >> 5;
    const int lane = threadIdx.x & 31;
    const int s = (warp / NH) % S_;
    float* p = t + (size_t)warp * HD_;

    float t1 = p[lane];
    float t2 = p[lane + 32];
    float ss = t1 * t1 + t2 * t2;
    #pragma unroll
    for (int o = 16; o > 0; o >>= 1) ss += __shfl_xor_sync(0xffffffffu, ss, o);
    float rs = rsqrtf(ss * (1.0f / HD_) + 1e-6f);

    float n1 = t1 * rs * (1.0f + scale[lane]);
    float n2 = t2 * rs * (1.0f + scale[lane + 32]);

    float c1 = cosp[s * HD_ + lane],      c2 = cosp[s * HD_ + lane + 32];
    float s1 = sinp[s * HD_ + lane],      s2 = sinp[s * HD_ + lane + 32];
    float o1 = (n1 * c1 - n2 * s1) * mul;
    float o2 = (n2 * c2 + n1 * s2) * mul;
    p[lane]      = o1;
    p[lane + 32] = o2;
}

// ---------------------------------------------------------------------------
// Tensor-core causal flash attention (bf16-split, FA2-style).
// Block = (b, h, 64 q-rows). 4 warps x 16 rows. Key tiles of 64.
// ---------------------------------------------------------------------------
#define TSTR 72
#define NEG_BIG (-1e30f)

__global__ __launch_bounds__(128) void attn_tc(
    const float* __restrict__ q, const float* __restrict__ k,
    const float* __restrict__ v, float* __restrict__ ctx)
{
    __shared__ __align__(16) __nv_bfloat16 Kh[64*TSTR];
    __shared__ __align__(16) __nv_bfloat16 Kl[64*TSTR];
    __shared__ __align__(16) __nv_bfloat16 Vh[64*TSTR];
    __shared__ __align__(16) __nv_bfloat16 Vl[64*TSTR];

    const int tid  = threadIdx.x;
    const int lane = tid & 31;
    const int warp = tid >> 5;
    const int qt = blockIdx.x, h = blockIdx.y, b = blockIdx.z;
    const int g  = h / GS_;
    const int q0 = qt * 64;

    const int a_lr = lane & 15;
    const int a_k8 = ((lane >> 4) & 1) << 3;
    const int b_nr = (((lane >> 4) & 1) << 3) | (lane & 7);
    const int b_k8 = ((lane >> 3) & 1) << 3;
    const int v_r  = lane & 15;

    // ---- Load Q once, split to bf16 hi/lo, fragments into registers ----
    #pragma unroll
    for (int it = 0; it < 8; it++) {
        int f = it * 128 + tid, row = f >> 4, c4 = f & 15;
        float4 val = *(const float4*)(q + (((size_t)(b * S_ + q0 + row)) * H_ + h) * HD_ + c4 * 4);
        uint2 hi, lo; cvt4(val, hi, lo);
        *(uint2*)&Kh[row * TSTR + c4 * 4] = hi;
        *(uint2*)&Kl[row * TSTR + c4 * 4] = lo;
    }
    __syncthreads();

    uint32 qh[4][4], ql[4][4];
    #pragma unroll
    for (int kc = 0; kc < 4; kc++) {
        int off = (warp * 16 + a_lr) * TSTR + kc * 16 + a_k8;
        ldsm4(qh[kc][0], qh[kc][1], qh[kc][2], qh[kc][3], &Kh[off]);
        ldsm4(ql[kc][0], ql[kc][1], ql[kc][2], ql[kc][3], &Kl[off]);
    }
    __syncthreads();

    float octx[8][4];
    #pragma unroll
    for (int i = 0; i < 8; i++)
        #pragma unroll
        for (int j = 0; j < 4; j++) octx[i][j] = 0.f;
    float m0 = NEG_BIG, m1 = NEG_BIG, l0 = 0.f, l1 = 0.f;

    for (int kt0 = 0; kt0 <= q0; kt0 += 64) {
        // ---- Load + split K, V tiles ----
        #pragma unroll
        for (int it = 0; it < 8; it++) {
            int f = it * 128 + tid, row = f >> 4, c4 = f & 15;
            size_t base = (((size_t)(b * S_ + kt0 + row)) * G_ + g) * HD_ + c4 * 4;
            uint2 hi, lo;
            cvt4(*(const float4*)(k + base), hi, lo);
            *(uint2*)&Kh[row * TSTR + c4 * 4] = hi;
            *(uint2*)&Kl[row * TSTR + c4 * 4] = lo;
            cvt4(*(const float4*)(v + base), hi, lo);
            *(uint2*)&Vh[row * TSTR + c4 * 4] = hi;
            *(uint2*)&Vl[row * TSTR + c4 * 4] = lo;
        }
        __syncthreads();

        // ---- Scores: S = Q K^T (split: QhKh + QlKh + QhKl) ----
        float sc[8][4];
        #pragma unroll
        for (int i = 0; i < 8; i++)
            #pragma unroll
            for (int j = 0; j < 4; j++) sc[i][j] = 0.f;

        #pragma unroll
        for (int kg = 0; kg < 4; kg++) {
            #pragma unroll
            for (int kc = 0; kc < 4; kc++) {
                uint32 bh0, bh1, bh2, bh3, bl0, bl1, bl2, bl3;
                int off = (kg * 16 + b_nr) * TSTR + kc * 16 + b_k8;
                ldsm4(bh0, bh1, bh2, bh3, &Kh[off]);
                ldsm4(bl0, bl1, bl2, bl3, &Kl[off]);
                mma16816(sc[2*kg],   qh[kc], bh0, bh1);
                mma16816(sc[2*kg],   ql[kc], bh0, bh1);
                mma16816(sc[2*kg],   qh[kc], bl0, bl1);
                mma16816(sc[2*kg+1], qh[kc], bh2, bh3);
                mma16816(sc[2*kg+1], ql[kc], bh2, bh3);
                mma16816(sc[2*kg+1], qh[kc], bl2, bl3);
            }
        }

        const int gq = lane >> 2, tt = lane & 3;
        // ---- Causal mask (only the diagonal tile needs it) ----
        if (kt0 == q0) {
            int qi0 = q0 + warp * 16 + gq;
            int qi1 = qi0 + 8;
            #pragma unroll
            for (int j = 0; j < 8; j++) {
                int kj = kt0 + j * 8 + tt * 2;
                if (kj     > qi0) sc[j][0] = NEG_BIG;
                if (kj + 1 > qi0) sc[j][1] = NEG_BIG;
                if (kj     > qi1) sc[j][2] = NEG_BIG;
                if (kj + 1 > qi1) sc[j][3] = NEG_BIG;
            }
        }

        // ---- Online softmax (register fragments, quad shuffles) ----
        float mx0 = NEG_BIG, mx1 = NEG_BIG;
        #pragma unroll
        for (int j = 0; j < 8; j++) {
            mx0 = fmaxf(mx0, fmaxf(sc[j][0], sc[j][1]));
            mx1 = fmaxf(mx1, fmaxf(sc[j][2], sc[j][3]));
        }
        #pragma unroll
        for (int o = 1; o <= 2; o <<= 1) {
            mx0 = fmaxf(mx0, __shfl_xor_sync(0xffffffffu, mx0, o));
            mx1 = fmaxf(mx1, __shfl_xor_sync(0xffffffffu, mx1, o));
        }
        mx0 = fmaxf(mx0, m0); mx1 = fmaxf(mx1, m1);
        float alpha0 = __expf(m0 - mx0), alpha1 = __expf(m1 - mx1);
        m0 = mx0; m1 = mx1;

        float s0 = 0.f, s1 = 0.f;
        #pragma unroll
        for (int j = 0; j < 8; j++) {
            sc[j][0] = __expf(sc[j][0] - m0); s0 += sc[j][0];
            sc[j][1] = __expf(sc[j][1] - m0); s0 += sc[j][1];
            sc[j][2] = __expf(sc[j][2] - m1); s1 += sc[j][2];
            sc[j][3] = __expf(sc[j][3] - m1); s1 += sc[j][3];
        }
        #pragma unroll
        for (int o = 1; o <= 2; o <<= 1) {
            s0 += __shfl_xor_sync(0xffffffffu, s0, o);
            s1 += __shfl_xor_sync(0xffffffffu, s1, o);
        }
        l0 = l0 * alpha0 + s0;
        l1 = l1 * alpha1 + s1;

        #pragma unroll
        for (int ni = 0; ni < 8; ni++) {
            octx[ni][0] *= alpha0; octx[ni][1] *= alpha0;
            octx[ni][2] *= alpha1; octx[ni][3] *= alpha1;
        }

        // ---- Build P fragments directly from score fragments (C->A identity) ----
        uint32 aph[4][4], apl[4][4];
        #pragma unroll
        for (int kc = 0; kc < 4; kc++) {
            split2(sc[2*kc][0],   sc[2*kc][1],   aph[kc][0], apl[kc][0]);
            split2(sc[2*kc][2],   sc[2*kc][3],   aph[kc][1], apl[kc][1]);
            split2(sc[2*kc+1][0], sc[2*kc+1][1], aph[kc][2], apl[kc][2]);
            split2(sc[2*kc+1][2], sc[2*kc+1][3], aph[kc][3], apl[kc][3]);
        }

        // ---- ctx += P @ V (split: PhVh + PhVl + PlVh), V via ldmatrix.trans ----
        #pragma unroll
        for (int ni = 0; ni < 8; ni++) {
            #pragma unroll
            for (int kc = 0; kc < 4; kc++) {
                uint32 vh0, vh1, vl0, vl1;
                int off = (kc * 16 + v_r) * TSTR + ni * 8;
                ldsm2t(vh0, vh1, &Vh[off]);
                ldsm2t(vl0, vl1, &Vl[off]);
                mma16816(octx[ni], aph[kc], vh0, vh1);
                mma16816(octx[ni], aph[kc], vl0, vl1);
                mma16816(octx[ni], apl[kc], vh0, vh1);
            }
        }
        __syncthreads();
    }

    // ---- Epilogue: normalize and write ----
    const int gq = lane >> 2, tt = lane & 3;
    float inv0 = 1.0f / l0, inv1 = 1.0f / l1;
    #pragma unroll
    for (int ni = 0; ni < 8; ni++) {
        int row = q0 + warp * 16 + gq;
        int col = ni * 8 + tt * 2;
        *(float2*)(ctx + (((size_t)(b * S_ + row)) * H_ + h) * HD_ + col) =
            make_float2(octx[ni][0] * inv0, octx[ni][1] * inv0);
        *(float2*)(ctx + (((size_t)(b * S_ + row + 8)) * H_ + h) * HD_ + col) =
            make_float2(octx[ni][2] * inv1, octx[ni][3] * inv1);
    }
}

// ---------------------------------------------------------------------------
// Launch
// ---------------------------------------------------------------------------
extern "C" void kernel_launch(void* const* d_in, const int* in_sizes, int n_in,
                              void* d_out, int out_size)
{
    (void)in_sizes; (void)n_in; (void)out_size;
    const float* x    = (const float*)d_in[0];
    const float* cosp = (const float*)d_in[2];
    const float* sinp = (const float*)d_in[3];
    const float* Wq   = (const float*)d_in[4];
    const float* Wk   = (const float*)d_in[5];
    const float* Wv   = (const float*)d_in[6];
    const float* Wo   = (const float*)d_in[7];
    const float* qsc  = (const float*)d_in[8];
    const float* ksc  = (const float*)d_in[9];
    float* out = (float*)d_out;

    float *pq, *pk, *pv, *pc;
    cudaGetSymbolAddress((void**)&pq, g_q);
    cudaGetSymbolAddress((void**)&pk, g_k);
    cudaGetSymbolAddress((void**)&pv, g_v);
    cudaGetSymbolAddress((void**)&pc, g_ctx);

    const int M = B_ * S_;  // 4096

    gemm_nt_tc<<<dim3((H_*HD_)/BN, M/BM), 256>>>(x, Wq, pq, M, H_*HD_, D_);
    gemm_nt_tc<<<dim3((G_*HD_)/BN, M/BM), 256>>>(x, Wk, pk, M, G_*HD_, D_);
    gemm_nt_tc<<<dim3((G_*HD_)/BN, M/BM), 256>>>(x, Wv, pv, M, G_*HD_, D_);

    rms_rope<<<(M * H_) / 8, 256>>>(pq, cosp, sinp, qsc, H_, 0.125f);
    rms_rope<<<(M * G_) / 8, 256>>>(pk, cosp, sinp, ksc, G_, 1.0f);

    attn_tc<<<dim3(S_/64, H_, B_), 128>>>(pq, pk, pv, pc);

    gemm_nt_tc<<<dim3(D_/BN, M/BM), 256>>>(pc, Wo, out, M, D_, H_*HD_);
}